// round 2
// baseline (speedup 1.0000x reference)
#include <cuda_runtime.h>
#include <math_constants.h>
#include <math.h>

#define B_   32
#define LQ   513
#define SK   1000
#define NH   8
#define DH   128
#define DM   1024
#define DLLM 4096
#define MQ   (B_*LQ)   /* 16416 */

// ---------------- scratch (no allocation allowed) ----------------
__device__ float g_tgt[(size_t)MQ * DM];    // [32*513, 1024]  concat(cls, target)
__device__ float g_q  [(size_t)MQ * DM];    // Q projection
__device__ float g_k  [(size_t)SK * DM];    // K projection
__device__ float g_v  [(size_t)SK * DM];    // V projection
__device__ float g_at [(size_t)MQ * DM];    // attention output (pre out-proj)

// ---------------- build tgt = [cls ; target_embedding] ----------------
__global__ void build_tgt_kernel(const float* __restrict__ tgt_emb,
                                 const float* __restrict__ cls,
                                 float* __restrict__ out)
{
    // float4 granularity: 16416 rows * 256 float4/row
    size_t i = (size_t)blockIdx.x * blockDim.x + threadIdx.x;
    size_t total = (size_t)MQ * (DM / 4);
    if (i >= total) return;
    size_t row = i / (DM / 4);
    int    c4  = (int)(i % (DM / 4));
    int b  = (int)(row / LQ);
    int lx = (int)(row % LQ);
    float4 v;
    if (lx == 0) v = ((const float4*)cls)[c4];
    else         v = ((const float4*)tgt_emb)[ ((size_t)b * (LQ-1) + (lx-1)) * (DM/4) + c4 ];
    ((float4*)out)[i] = v;
}

// ---------------- generic SGEMM: C[M,N] = A[M,K] @ B[K,N] + bias ----------------
// 128x128 tile, BK=8, 256 threads, 8x8 micro-tile per thread.
__global__ __launch_bounds__(256) void sgemm_kernel(
    const float* __restrict__ A, const float* __restrict__ B,
    const float* __restrict__ bias, float* __restrict__ C,
    int M, int N, int K)
{
    __shared__ float As[8][128];
    __shared__ float Bs[8][128];

    const int tid = threadIdx.x;
    const int tx = tid & 15;        // 0..15  (N micro)
    const int ty = tid >> 4;        // 0..15  (M micro)
    const int rowBase = blockIdx.y * 128;
    const int colBase = blockIdx.x * 128;

    // A-load mapping: each thread loads one float4 (row mA, k offset kA)
    const int mA = tid >> 1;        // 0..127
    const int kA = (tid & 1) * 4;   // 0 or 4
    // B-load mapping: contiguous float4 over [8][128]
    const int bIdx = tid * 4;
    const int bkk  = bIdx >> 7;     // 0..7
    const int bn   = bIdx & 127;

    float acc[8][8];
    #pragma unroll
    for (int i = 0; i < 8; i++)
        #pragma unroll
        for (int j = 0; j < 8; j++) acc[i][j] = 0.f;

    for (int k0 = 0; k0 < K; k0 += 8) {
        // load A tile (guard M), transpose into As[k][m]
        float4 a4 = make_float4(0.f, 0.f, 0.f, 0.f);
        int gr = rowBase + mA;
        if (gr < M) a4 = *(const float4*)&A[(size_t)gr * K + k0 + kA];
        As[kA + 0][mA] = a4.x;
        As[kA + 1][mA] = a4.y;
        As[kA + 2][mA] = a4.z;
        As[kA + 3][mA] = a4.w;
        // load B tile (N,K guaranteed multiples of 128/8 in this problem)
        float4 b4 = *(const float4*)&B[(size_t)(k0 + bkk) * N + colBase + bn];
        *(float4*)&Bs[bkk][bn] = b4;
        __syncthreads();

        #pragma unroll
        for (int kk = 0; kk < 8; kk++) {
            float a[8], b[8];
            *(float4*)&a[0] = *(float4*)&As[kk][ty * 8];
            *(float4*)&a[4] = *(float4*)&As[kk][ty * 8 + 4];
            *(float4*)&b[0] = *(float4*)&Bs[kk][tx * 8];
            *(float4*)&b[4] = *(float4*)&Bs[kk][tx * 8 + 4];
            #pragma unroll
            for (int i = 0; i < 8; i++)
                #pragma unroll
                for (int j = 0; j < 8; j++)
                    acc[i][j] += a[i] * b[j];
        }
        __syncthreads();
    }

    // epilogue (+bias)
    #pragma unroll
    for (int i = 0; i < 8; i++) {
        int gr = rowBase + ty * 8 + i;
        if (gr >= M) continue;
        #pragma unroll
        for (int j = 0; j < 8; j += 4) {
            int gc = colBase + tx * 8 + j;
            float4 o;
            o.x = acc[i][j + 0] + bias[gc + 0];
            o.y = acc[i][j + 1] + bias[gc + 1];
            o.z = acc[i][j + 2] + bias[gc + 2];
            o.w = acc[i][j + 3] + bias[gc + 3];
            *(float4*)&C[(size_t)gr * N + gc] = o;
        }
    }
}

// ---------------- fused attention (flash-style, fp32) ----------------
// grid: (ceil(513/64)=9, H=8, B=32), 256 threads.
// Each thread owns one Q row (row = tid/4) and 32 interleaved output cols
// (col = 4*c + cg, cg = tid%3... tid&3).
#define BQ 64
#define BS 32
#define QPITCH (DH + 4)   // 132, pad kills stride-128 bank conflicts
#define SPITCH (BS + 1)   // 33

#define SMEM_ATTN ((BQ*QPITCH + 2*BS*QPITCH + BQ*SPITCH) * (int)sizeof(float))

__global__ __launch_bounds__(256) void attn_kernel()
{
    extern __shared__ float sm[];
    float* Qs = sm;                         // [BQ][QPITCH]
    float* Ks = Qs + BQ * QPITCH;           // [BS][QPITCH]
    float* Vs = Ks + BS * QPITCH;           // [BS][QPITCH]
    float* Ss = Vs + BS * QPITCH;           // [BQ][SPITCH]

    const int tid = threadIdx.x;
    const int qt = blockIdx.x, h = blockIdx.y, b = blockIdx.z;
    const int q0 = qt * BQ;
    const int row = tid >> 2;   // 0..63
    const int cg  = tid & 3;    // 0..3
    const float SCALE = 0.08838834764831845f; // 1/sqrt(128)

    // load Q tile
    for (int i = tid; i < BQ * (DH / 4); i += 256) {
        int r = i / (DH / 4);
        int c4 = (i % (DH / 4)) * 4;
        float4 v = make_float4(0.f, 0.f, 0.f, 0.f);
        int gq = q0 + r;
        if (gq < LQ)
            v = *(const float4*)&g_q[((size_t)b * LQ + gq) * DM + h * DH + c4];
        *(float4*)&Qs[r * QPITCH + c4] = v;
    }

    float acc[32];
    #pragma unroll
    for (int c = 0; c < 32; c++) acc[c] = 0.f;
    float m = -CUDART_INF_F, l = 0.f;

    for (int s0 = 0; s0 < SK; s0 += BS) {
        __syncthreads();   // previous tile's consumers done
        // load K,V tiles
        for (int i = tid; i < BS * (DH / 4); i += 256) {
            int r = i / (DH / 4);
            int c4 = (i % (DH / 4)) * 4;
            int gs = s0 + r;
            float4 kv = make_float4(0.f, 0.f, 0.f, 0.f);
            float4 vv = kv;
            if (gs < SK) {
                kv = *(const float4*)&g_k[(size_t)gs * DM + h * DH + c4];
                vv = *(const float4*)&g_v[(size_t)gs * DM + h * DH + c4];
            }
            *(float4*)&Ks[r * QPITCH + c4] = kv;
            *(float4*)&Vs[r * QPITCH + c4] = vv;
        }
        __syncthreads();

        // scores: this thread computes cols {4j+cg}
        float dot[8];
        #pragma unroll
        for (int j = 0; j < 8; j++) dot[j] = 0.f;
        #pragma unroll 8
        for (int e = 0; e < DH; e += 4) {
            float4 qv = *(float4*)&Qs[row * QPITCH + e];
            #pragma unroll
            for (int j = 0; j < 8; j++) {
                float4 kv = *(float4*)&Ks[(4 * j + cg) * QPITCH + e];
                dot[j] += qv.x * kv.x + qv.y * kv.y + qv.z * kv.z + qv.w * kv.w;
            }
        }
        #pragma unroll
        for (int j = 0; j < 8; j++) {
            int col = 4 * j + cg;
            Ss[row * SPITCH + col] = (s0 + col < SK) ? dot[j] * SCALE : -CUDART_INF_F;
        }
        __syncthreads();

        // online softmax update (redundant across the 4 threads of a row quad)
        float tm = -CUDART_INF_F;
        #pragma unroll
        for (int c = 0; c < BS; c++) tm = fmaxf(tm, Ss[row * SPITCH + c]);
        float mnew  = fmaxf(m, tm);
        float alpha = __expf(m - mnew);
        l *= alpha;
        #pragma unroll
        for (int c = 0; c < 32; c++) acc[c] *= alpha;
        for (int k = 0; k < BS; k++) {
            float pk = __expf(Ss[row * SPITCH + k] - mnew);
            l += pk;
            const float* vrow = &Vs[k * QPITCH];
            #pragma unroll
            for (int c = 0; c < 32; c++)
                acc[c] += pk * vrow[4 * c + cg];
        }
        m = mnew;
    }

    // epilogue
    int gq = q0 + row;
    if (gq < LQ) {
        float inv = 1.0f / l;
        size_t base = ((size_t)b * LQ + gq) * DM + h * DH;
        #pragma unroll
        for (int c = 0; c < 32; c++)
            g_at[base + 4 * c + cg] = acc[c] * inv;
    }
}

// ---------------- launcher ----------------
extern "C" void kernel_launch(void* const* d_in, const int* in_sizes, int n_in,
                              void* d_out, int out_size)
{
    const float* tgt = (const float*)d_in[0];
    const float* src = (const float*)d_in[1];
    const float* val = (const float*)d_in[2];
    const float* Wq  = (const float*)d_in[3];
    const float* bq  = (const float*)d_in[4];
    const float* Wk  = (const float*)d_in[5];
    const float* bk  = (const float*)d_in[6];
    const float* Wv  = (const float*)d_in[7];
    const float* bv  = (const float*)d_in[8];
    const float* Wo  = (const float*)d_in[9];
    const float* bo  = (const float*)d_in[10];
    const float* cls = (const float*)d_in[11];

    float *p_tgt, *p_q, *p_k, *p_v, *p_at;
    cudaGetSymbolAddress((void**)&p_tgt, g_tgt);
    cudaGetSymbolAddress((void**)&p_q,   g_q);
    cudaGetSymbolAddress((void**)&p_k,   g_k);
    cudaGetSymbolAddress((void**)&p_v,   g_v);
    cudaGetSymbolAddress((void**)&p_at,  g_at);

    // 1) tgt = [cls ; target]
    {
        size_t total = (size_t)MQ * (DM / 4);
        int blocks = (int)((total + 255) / 256);
        build_tgt_kernel<<<blocks, 256>>>(tgt, cls, p_tgt);
    }
    // 2) Q = tgt @ Wq + bq        [16416,1024] = [16416,1024]@[1024,1024]
    sgemm_kernel<<<dim3(DM / 128, (MQ + 127) / 128), 256>>>(p_tgt, Wq, bq, p_q, MQ, DM, DM);
    // 3) K = src @ Wk + bk        [1000,1024] = [1000,4096]@[4096,1024]
    sgemm_kernel<<<dim3(DM / 128, (SK + 127) / 128), 256>>>(src, Wk, bk, p_k, SK, DM, DLLM);
    // 4) V = val @ Wv + bv
    sgemm_kernel<<<dim3(DM / 128, (SK + 127) / 128), 256>>>(val, Wv, bv, p_v, SK, DM, DLLM);
    // 5) attention
    cudaFuncSetAttribute(attn_kernel, cudaFuncAttributeMaxDynamicSharedMemorySize, SMEM_ATTN);
    attn_kernel<<<dim3((LQ + BQ - 1) / BQ, NH, B_), 256, SMEM_ATTN>>>();
    // 6) out = attn @ Wo + bo     [16416,4096] = [16416,1024]@[1024,4096]
    sgemm_kernel<<<dim3(DLLM / 128, (MQ + 127) / 128), 256>>>(p_at, Wo, bo, (float*)d_out, MQ, DLLM, DM);
}